// round 4
// baseline (speedup 1.0000x reference)
#include <cuda_runtime.h>
#include <cstdint>
#include <cstddef>

#define B_   8
#define N_   512
#define FIN  128
#define FOUT 64
#define ALPHA 0.2f

// Scratch (no allocations allowed)
__device__ float g_Wh[B_ * N_ * FOUT];   // 1 MB
__device__ float g_ei[B_ * N_];
__device__ float g_ej[B_ * N_];

// ---------------------------------------------------------------------------
// Stage 1: Wh = h @ W ; e_i = Wh·a_i ; e_j = Wh·a_j
// Grid: 512 CTAs, 256 threads. 8 i-rows per CTA.
// ---------------------------------------------------------------------------
__global__ __launch_bounds__(256)
void gat_stage1(const float* __restrict__ h,
                const float* __restrict__ W,
                const float* __restrict__ a)
{
    __shared__ float Wt[FOUT * 129];
    __shared__ float h_s[8 * FIN];
    __shared__ float wh_s[8 * 65];

    const int t = threadIdx.x;
    const int b  = blockIdx.x >> 6;          // 64 tiles per batch
    const int i0 = (blockIdx.x & 63) * 8;

    for (int idx = t; idx < FIN * FOUT; idx += 256) {
        int k = idx >> 6, o = idx & 63;
        Wt[o * 129 + k] = W[idx];
    }
    {
        const float4* hb = (const float4*)(h + ((size_t)(b * N_ + i0)) * FIN);
        float4* hs4 = (float4*)h_s;
        for (int idx = t; idx < 8 * FIN / 4; idx += 256) hs4[idx] = hb[idx];
    }
    __syncthreads();

    const int o = t & 63, grp = t >> 6;
    float acc0 = 0.f, acc1 = 0.f;
    const float* hb = h_s + grp * 2 * FIN;
    #pragma unroll 8
    for (int k = 0; k < FIN; k++) {
        float w = Wt[o * 129 + k];
        acc0 += hb[k] * w;
        acc1 += hb[FIN + k] * w;
    }
    wh_s[(grp * 2 + 0) * 65 + o] = acc0;
    wh_s[(grp * 2 + 1) * 65 + o] = acc1;
    g_Wh[((size_t)(b * N_ + i0 + grp * 2 + 0)) * FOUT + o] = acc0;
    g_Wh[((size_t)(b * N_ + i0 + grp * 2 + 1)) * FOUT + o] = acc1;
    __syncthreads();

    const int wid = t >> 5, lane = t & 31;
    {
        int row = wid;   // 8 warps, 8 rows
        float v1 = wh_s[row * 65 + lane];
        float v2 = wh_s[row * 65 + lane + 32];
        float si = v1 * a[lane]      + v2 * a[lane + 32];
        float sj = v1 * a[64 + lane] + v2 * a[96 + lane];
        #pragma unroll
        for (int off = 16; off > 0; off >>= 1) {
            si += __shfl_xor_sync(0xffffffffu, si, off);
            sj += __shfl_xor_sync(0xffffffffu, sj, off);
        }
        if (lane == 0) {
            g_ei[b * N_ + i0 + row] = si;
            g_ej[b * N_ + i0 + row] = sj;
        }
    }
}

// ---------------------------------------------------------------------------
// Stage 2: fused edge projection + leakyrelu + exp + softmax-sum + attn@Wh
// Grid: B_ * (N_/4) = 1024 CTAs, 256 threads. TI = 4 rows per CTA.
// grid >> resident slots -> scheduler backfill smooths wave imbalance.
// ---------------------------------------------------------------------------
#define TI 4

__global__ __launch_bounds__(256, 6)
void gat_stage2(const float* __restrict__ edge,
                const float* __restrict__ U,
                const float* __restrict__ a,
                float* __restrict__ out)
{
    __shared__ __align__(16) float es_f[N_ * TI];       // exp(e)[j][ti]  8 KB
    __shared__ __align__(16) float pool[4 * TI * FOUT]; // ej_s (2KB) / red_c (4KB)
    __shared__ float4 u_s[16];
    __shared__ float  wsum[TI * 8];                     // [ti][warp]
    __shared__ float  rowsum[TI];

    const int t    = threadIdx.x;
    const int b    = blockIdx.x >> 7;                   // 128 tiles per batch
    const int i0   = (blockIdx.x & 127) * TI;
    const int wid  = t >> 5, lane = t & 31;
    const int half = lane >> 4, sub = lane & 15;

    const float a_e = __ldg(a + 2 * FOUT);
    float* ej_s = pool;                                 // first 512 floats
    if (t < 16) {
        float4 u = ((const float4*)U)[t];
        u.x *= a_e; u.y *= a_e; u.z *= a_e; u.w *= a_e; // fold a_e into U
        u_s[t] = u;
    }
    ej_s[t]       = g_ej[b * N_ + t];
    ej_s[t + 256] = g_ej[b * N_ + t + 256];
    float ei[TI];
    #pragma unroll
    for (int ti = 0; ti < TI; ti++) ei[ti] = __ldg(g_ei + b * N_ + i0 + ti);
    __syncthreads();

    const float4 u4 = u_s[sub];

    // --- Phase A: warp w handles j in [w*64, w*64+64), all TI rows.
    // 16 lanes cooperate per 256B j-row; exp fused; row-sums on the fly.
    #pragma unroll
    for (int ti = 0; ti < TI; ti++) {
        const float4* rb =
            (const float4*)(edge + ((size_t)(b * N_ + i0 + ti)) * N_ * FOUT);
        const float eiv = ei[ti];
        float psum = 0.f;
        #pragma unroll 8
        for (int jj = 0; jj < 32; jj++) {
            int j = wid * 64 + jj * 2 + half;
            float4 v = rb[(size_t)j * 16 + sub];
            float s = v.x * u4.x + v.y * u4.y + v.z * u4.z + v.w * u4.w;
            #pragma unroll
            for (int off = 8; off > 0; off >>= 1)
                s += __shfl_xor_sync(0xffffffffu, s, off);
            float val = eiv + ej_s[j] + s;
            val = (val >= 0.f) ? val : ALPHA * val;
            float ev = __expf(val);
            if (sub == 0) {
                es_f[j * TI + ti] = ev;
                psum += ev;
            }
        }
        psum += __shfl_xor_sync(0xffffffffu, psum, 16);
        if (lane == 0) wsum[ti * 8 + wid] = psum;
    }
    __syncthreads();

    if (t < TI) {
        float ss = wsum[t * 8 + 0];
        #pragma unroll
        for (int w = 1; w < 8; w++) ss += wsum[t * 8 + w];
        rowsum[t] = ss;
    }
    __syncthreads();   // pool reuse barrier (ej_s -> red_c) + rowsum ready

    // --- Phase C: acc[ti] = sum_j p[ti][j] * Wh[b,j,o], j split in 4 groups ---
    float* red_c = pool;
    {
        const int g = t >> 6, o = t & 63;
        const float* WhB = g_Wh + (size_t)b * N_ * FOUT;
        float acc0 = 0.f, acc1 = 0.f, acc2 = 0.f, acc3 = 0.f;
        const int jbase = g * 128;
        #pragma unroll 4
        for (int jj = 0; jj < 128; jj++) {
            int j = jbase + jj;
            float w = __ldg(WhB + (size_t)j * FOUT + o);
            float4 ea = *(const float4*)&es_f[j * TI];
            acc0 += ea.x * w; acc1 += ea.y * w;
            acc2 += ea.z * w; acc3 += ea.w * w;
        }
        red_c[(g * TI + 0) * FOUT + o] = acc0;
        red_c[(g * TI + 1) * FOUT + o] = acc1;
        red_c[(g * TI + 2) * FOUT + o] = acc2;
        red_c[(g * TI + 3) * FOUT + o] = acc3;
    }
    __syncthreads();
    // epilogue: 256 outputs, 1 per thread, normalize by row sum
    {
        const int ti = t >> 6, o = t & 63;
        float r = red_c[(0 * TI + ti) * FOUT + o]
                + red_c[(1 * TI + ti) * FOUT + o]
                + red_c[(2 * TI + ti) * FOUT + o]
                + red_c[(3 * TI + ti) * FOUT + o];
        r *= __frcp_rn(rowsum[ti]);
        out[((size_t)(b * N_ + i0 + ti)) * FOUT + o] = r;
    }
}

// ---------------------------------------------------------------------------
extern "C" void kernel_launch(void* const* d_in, const int* in_sizes, int n_in,
                              void* d_out, int out_size)
{
    const float* h    = (const float*)d_in[0];   // [8,512,128]
    const float* edge = (const float*)d_in[1];   // [8,512,512,64]
    const float* W    = (const float*)d_in[2];   // [1,128,64]
    const float* U    = (const float*)d_in[3];   // [1,64]
    const float* a    = (const float*)d_in[4];   // [1,129]
    float* out = (float*)d_out;                  // [8,512,64]

    gat_stage1<<<B_ * (N_ / 8), 256>>>(h, W, a);
    gat_stage2<<<B_ * (N_ / TI), 256>>>(edge, U, a, out);
}

// round 5
// speedup vs baseline: 1.2813x; 1.2813x over previous
#include <cuda_runtime.h>
#include <cstdint>
#include <cstddef>

#define B_   8
#define N_   512
#define FIN  128
#define FOUT 64
#define ALPHA 0.2f

// Scratch (no allocations allowed)
__device__ float g_Wh[B_ * N_ * FOUT];   // 1 MB
__device__ float g_ei[B_ * N_];
__device__ float g_ej[B_ * N_];

// ---------------------------------------------------------------------------
// Stage 1: Wh = h @ W ; e_i = Wh·a_i ; e_j = Wh·a_j
// Grid: 512 CTAs, 256 threads. 8 i-rows per CTA.
// ---------------------------------------------------------------------------
__global__ __launch_bounds__(256)
void gat_stage1(const float* __restrict__ h,
                const float* __restrict__ W,
                const float* __restrict__ a)
{
    __shared__ float Wt[FOUT * 129];
    __shared__ float h_s[8 * FIN];
    __shared__ float wh_s[8 * 65];

    const int t = threadIdx.x;
    const int b  = blockIdx.x >> 6;          // 64 tiles per batch
    const int i0 = (blockIdx.x & 63) * 8;

    for (int idx = t; idx < FIN * FOUT; idx += 256) {
        int k = idx >> 6, o = idx & 63;
        Wt[o * 129 + k] = W[idx];
    }
    {
        const float4* hb = (const float4*)(h + ((size_t)(b * N_ + i0)) * FIN);
        float4* hs4 = (float4*)h_s;
        for (int idx = t; idx < 8 * FIN / 4; idx += 256) hs4[idx] = hb[idx];
    }
    __syncthreads();

    const int o = t & 63, grp = t >> 6;
    float acc0 = 0.f, acc1 = 0.f;
    const float* hb = h_s + grp * 2 * FIN;
    #pragma unroll 8
    for (int k = 0; k < FIN; k++) {
        float w = Wt[o * 129 + k];
        acc0 += hb[k] * w;
        acc1 += hb[FIN + k] * w;
    }
    wh_s[(grp * 2 + 0) * 65 + o] = acc0;
    wh_s[(grp * 2 + 1) * 65 + o] = acc1;
    g_Wh[((size_t)(b * N_ + i0 + grp * 2 + 0)) * FOUT + o] = acc0;
    g_Wh[((size_t)(b * N_ + i0 + grp * 2 + 1)) * FOUT + o] = acc1;
    __syncthreads();

    const int wid = t >> 5, lane = t & 31;
    {
        int row = wid;   // 8 warps, 8 rows
        float v1 = wh_s[row * 65 + lane];
        float v2 = wh_s[row * 65 + lane + 32];
        float si = v1 * a[lane]      + v2 * a[lane + 32];
        float sj = v1 * a[64 + lane] + v2 * a[96 + lane];
        #pragma unroll
        for (int off = 16; off > 0; off >>= 1) {
            si += __shfl_xor_sync(0xffffffffu, si, off);
            sj += __shfl_xor_sync(0xffffffffu, sj, off);
        }
        if (lane == 0) {
            g_ei[b * N_ + i0 + row] = si;
            g_ej[b * N_ + i0 + row] = sj;
        }
    }
}

// ---------------------------------------------------------------------------
// Stage 2: fused edge projection + leakyrelu + exp + softmax-sum + attn@Wh
// Grid: B_ * (N_/8) = 512 CTAs, 256 threads. TI = 8 rows per CTA.
// Phase A: 8 lanes cooperate per 256B j-row; each warp-iteration covers
// 4 rows with 2 full-line LDG.128 per lane and ONE 3-shfl butterfly that
// reduces all 4 rows at once.
// ---------------------------------------------------------------------------
#define TI 8

__global__ __launch_bounds__(256, 4)
void gat_stage2(const float* __restrict__ edge,
                const float* __restrict__ U,
                const float* __restrict__ a,
                float* __restrict__ out)
{
    __shared__ __align__(16) float es_f[N_ * TI];       // exp(e)[j][ti] 16 KB
    __shared__ __align__(16) float pool[4 * TI * FOUT]; // ej_s (2KB) / red_c (8KB)
    __shared__ float4 u_s[16];
    __shared__ float  wsum[TI * 8];                     // [ti][warp]
    __shared__ float  rowsum[TI];

    const int t    = threadIdx.x;
    const int b    = blockIdx.x >> 6;                   // 64 tiles per batch
    const int i0   = (blockIdx.x & 63) * TI;
    const int wid  = t >> 5, lane = t & 31;
    const int g3   = lane >> 3, s8 = lane & 7;

    const float a_e = __ldg(a + 2 * FOUT);
    float* ej_s = pool;                                 // first 512 floats
    if (t < 16) {
        float4 u = ((const float4*)U)[t];
        u.x *= a_e; u.y *= a_e; u.z *= a_e; u.w *= a_e; // fold a_e into U
        u_s[t] = u;
    }
    ej_s[t]       = g_ej[b * N_ + t];
    ej_s[t + 256] = g_ej[b * N_ + t + 256];
    float ei[TI];
    #pragma unroll
    for (int ti = 0; ti < TI; ti++) ei[ti] = __ldg(g_ei + b * N_ + i0 + ti);
    __syncthreads();

    const float4 u4a = u_s[s8];
    const float4 u4b = u_s[s8 + 8];

    // --- Phase A: warp w handles j in [w*64, w*64+64), all TI rows ---
    #pragma unroll
    for (int ti = 0; ti < TI; ti++) {
        const float4* rb =
            (const float4*)(edge + ((size_t)(b * N_ + i0 + ti)) * N_ * FOUT);
        const float eiv = ei[ti];
        float psum = 0.f;
        #pragma unroll 4
        for (int it = 0; it < 16; it++) {
            int j = wid * 64 + it * 4 + g3;
            const float4* p = rb + (size_t)j * 16;
            float4 v0 = p[s8];                 // bytes [s8*16 .. ) of row
            float4 v1 = p[s8 + 8];             // second 128B line
            float s = v0.x * u4a.x + v0.y * u4a.y + v0.z * u4a.z + v0.w * u4a.w
                    + v1.x * u4b.x + v1.y * u4b.y + v1.z * u4b.z + v1.w * u4b.w;
            // butterfly over the 8-lane group: reduces all 4 rows at once
            #pragma unroll
            for (int off = 4; off > 0; off >>= 1)
                s += __shfl_xor_sync(0xffffffffu, s, off);
            if (s8 == 0) {
                float val = eiv + ej_s[j] + s;
                val = fmaxf(val, ALPHA * val);     // leaky relu (alpha > 0)
                float ev = __expf(val);
                es_f[j * TI + ti] = ev;
                psum += ev;
            }
        }
        // psum valid on lanes 0,8,16,24 -> combine to lane 0
        psum += __shfl_xor_sync(0xffffffffu, psum, 8);
        psum += __shfl_xor_sync(0xffffffffu, psum, 16);
        if (lane == 0) wsum[ti * 8 + wid] = psum;
    }
    __syncthreads();

    if (t < TI) {
        float ss = wsum[t * 8 + 0];
        #pragma unroll
        for (int w = 1; w < 8; w++) ss += wsum[t * 8 + w];
        rowsum[t] = ss;
    }
    __syncthreads();   // pool reuse barrier (ej_s -> red_c) + rowsum ready

    // --- Phase C: acc[ti] = sum_j p[ti][j] * Wh[b,j,o], j split in 4 groups ---
    float* red_c = pool;
    {
        const int g = t >> 6, o = t & 63;
        const float* WhB = g_Wh + (size_t)b * N_ * FOUT;
        float acc[TI];
        #pragma unroll
        for (int ti = 0; ti < TI; ti++) acc[ti] = 0.f;
        const int jbase = g * 128;
        #pragma unroll 2
        for (int jj = 0; jj < 128; jj++) {
            int j = jbase + jj;
            float w = __ldg(WhB + (size_t)j * FOUT + o);
            float4 ea = *(const float4*)&es_f[j * TI];
            float4 eb = *(const float4*)&es_f[j * TI + 4];
            acc[0] += ea.x * w; acc[1] += ea.y * w;
            acc[2] += ea.z * w; acc[3] += ea.w * w;
            acc[4] += eb.x * w; acc[5] += eb.y * w;
            acc[6] += eb.z * w; acc[7] += eb.w * w;
        }
        #pragma unroll
        for (int ti = 0; ti < TI; ti++)
            red_c[(g * TI + ti) * FOUT + o] = acc[ti];
    }
    __syncthreads();
    // epilogue: 512 outputs, 2 per thread, normalize by row sum
    #pragma unroll
    for (int rep = 0; rep < 2; rep++) {
        int idx = t + rep * 256;
        int ti = idx >> 6, o = idx & 63;
        float r = red_c[(0 * TI + ti) * FOUT + o]
                + red_c[(1 * TI + ti) * FOUT + o]
                + red_c[(2 * TI + ti) * FOUT + o]
                + red_c[(3 * TI + ti) * FOUT + o];
        r *= __frcp_rn(rowsum[ti]);
        out[((size_t)(b * N_ + i0 + ti)) * FOUT + o] = r;
    }
}

// ---------------------------------------------------------------------------
extern "C" void kernel_launch(void* const* d_in, const int* in_sizes, int n_in,
                              void* d_out, int out_size)
{
    const float* h    = (const float*)d_in[0];   // [8,512,128]
    const float* edge = (const float*)d_in[1];   // [8,512,512,64]
    const float* W    = (const float*)d_in[2];   // [1,128,64]
    const float* U    = (const float*)d_in[3];   // [1,64]
    const float* a    = (const float*)d_in[4];   // [1,129]
    float* out = (float*)d_out;                  // [8,512,64]

    gat_stage1<<<B_ * (N_ / 8), 256>>>(h, W, a);
    gat_stage2<<<B_ * (N_ / TI), 256>>>(edge, U, a, out);
}

// round 6
// speedup vs baseline: 1.2845x; 1.0025x over previous
#include <cuda_runtime.h>
#include <cstdint>
#include <cstddef>

#define B_   8
#define N_   512
#define FIN  128
#define FOUT 64
#define ALPHA 0.2f

// Scratch (no allocations allowed)
__device__ float g_Wh[B_ * N_ * FOUT];   // 1 MB
__device__ float g_ei[B_ * N_];
__device__ float g_ej[B_ * N_];

// ---------------------------------------------------------------------------
// Stage 1: Wh = h @ W ; e_i = Wh·a_i ; e_j = Wh·a_j
// ---------------------------------------------------------------------------
__global__ __launch_bounds__(256)
void gat_stage1(const float* __restrict__ h,
                const float* __restrict__ W,
                const float* __restrict__ a)
{
    __shared__ float Wt[FOUT * 129];
    __shared__ float h_s[8 * FIN];
    __shared__ float wh_s[8 * 65];

    const int t = threadIdx.x;
    const int b  = blockIdx.x >> 6;
    const int i0 = (blockIdx.x & 63) * 8;

    for (int idx = t; idx < FIN * FOUT; idx += 256) {
        int k = idx >> 6, o = idx & 63;
        Wt[o * 129 + k] = W[idx];
    }
    {
        const float4* hb = (const float4*)(h + ((size_t)(b * N_ + i0)) * FIN);
        float4* hs4 = (float4*)h_s;
        for (int idx = t; idx < 8 * FIN / 4; idx += 256) hs4[idx] = hb[idx];
    }
    __syncthreads();

    const int o = t & 63, grp = t >> 6;
    float acc0 = 0.f, acc1 = 0.f;
    const float* hb = h_s + grp * 2 * FIN;
    #pragma unroll 8
    for (int k = 0; k < FIN; k++) {
        float w = Wt[o * 129 + k];
        acc0 += hb[k] * w;
        acc1 += hb[FIN + k] * w;
    }
    wh_s[(grp * 2 + 0) * 65 + o] = acc0;
    wh_s[(grp * 2 + 1) * 65 + o] = acc1;
    g_Wh[((size_t)(b * N_ + i0 + grp * 2 + 0)) * FOUT + o] = acc0;
    g_Wh[((size_t)(b * N_ + i0 + grp * 2 + 1)) * FOUT + o] = acc1;
    __syncthreads();

    const int wid = t >> 5, lane = t & 31;
    {
        int row = wid;
        float v1 = wh_s[row * 65 + lane];
        float v2 = wh_s[row * 65 + lane + 32];
        float si = v1 * a[lane]      + v2 * a[lane + 32];
        float sj = v1 * a[64 + lane] + v2 * a[96 + lane];
        #pragma unroll
        for (int off = 16; off > 0; off >>= 1) {
            si += __shfl_xor_sync(0xffffffffu, si, off);
            sj += __shfl_xor_sync(0xffffffffu, sj, off);
        }
        if (lane == 0) {
            g_ei[b * N_ + i0 + row] = si;
            g_ej[b * N_ + i0 + row] = sj;
        }
    }
}

// ---------------------------------------------------------------------------
// Stage 2: cp.async-pipelined edge stream + leakyrelu + exp + softmax + attn@Wh
// Grid: 512 CTAs, 256 threads, TI = 8. Warp w owns j in [w*64,(w+1)*64).
// Streaming: per-warp double-buffered 1KB chunks (4 j-rows), cp.async.cg,
// no block barriers in the hot loop.
// ---------------------------------------------------------------------------
#define TI 8

__device__ __forceinline__ void cp_async16(uint32_t dst, const float* src) {
    asm volatile("cp.async.cg.shared.global [%0], [%1], 16;" :: "r"(dst), "l"(src));
}

__global__ __launch_bounds__(256, 5)
void gat_stage2(const float* __restrict__ edge,
                const float* __restrict__ U,
                const float* __restrict__ a,
                float* __restrict__ out)
{
    __shared__ __align__(16) float stage_s[8 * 2 * 256];  // [warp][stage][1KB] 16 KB
    __shared__ __align__(16) float es_f[N_ * TI];         // exp(e)[j][ti]    16 KB
    __shared__ __align__(16) float pool[4 * TI * FOUT];   // ej_s / red_c      8 KB
    __shared__ float4 u_s[16];
    __shared__ float  ei_s[TI];
    __shared__ float  wsum[TI * 8];
    __shared__ float  rowsum[TI];

    const int t    = threadIdx.x;
    const int b    = blockIdx.x >> 6;
    const int i0   = (blockIdx.x & 63) * TI;
    const int wid  = t >> 5, lane = t & 31;
    const int g3   = lane >> 3, s8 = lane & 7;

    const float a_e = __ldg(a + 2 * FOUT);
    float* ej_s = pool;
    if (t < 16) {
        float4 u = ((const float4*)U)[t];
        u.x *= a_e; u.y *= a_e; u.z *= a_e; u.w *= a_e;
        u_s[t] = u;
    }
    if (t < TI) ei_s[t] = g_ei[b * N_ + i0 + t];
    ej_s[t]       = g_ej[b * N_ + t];
    ej_s[t + 256] = g_ej[b * N_ + t + 256];
    __syncthreads();

    const float4 u4a = u_s[s8];
    const float4 u4b = u_s[s8 + 8];

    // --- Phase A: per-warp cp.async pipeline over 128 chunks of 1 KB ---
    const float* wbase = edge + ((size_t)(b * N_ + i0) * N_ + wid * 64) * FOUT;
    const uint32_t stg =
        (uint32_t)__cvta_generic_to_shared(&stage_s[wid * 512]) + lane * 16;

    // chunk c: ti = c>>4, sub = c&15; 4 rows j = wid*64 + sub*4 + {0..3}
    // global offset (floats): ti*N*FOUT + sub*4*FOUT = ti*32768 + sub*256
    {
        // prologue: chunk 0
        cp_async16(stg,       wbase + lane * 4);
        cp_async16(stg + 512, wbase + lane * 4 + 128);
        asm volatile("cp.async.commit_group;" ::: "memory");
    }

    float psum = 0.f;
    for (int c = 0; c < 128; c++) {
        __syncwarp();                      // all lanes done reading stage (c+1)&1
        if (c < 127) {
            int cn = c + 1;
            const float* gsrc = wbase + (cn >> 4) * (N_ * FOUT)
                                      + (cn & 15) * (4 * FOUT) + lane * 4;
            uint32_t dst = stg + (cn & 1) * 1024;
            cp_async16(dst,       gsrc);
            cp_async16(dst + 512, gsrc + 128);
            asm volatile("cp.async.commit_group;" ::: "memory");
            asm volatile("cp.async.wait_group 1;" ::: "memory");
        } else {
            asm volatile("cp.async.wait_group 0;" ::: "memory");
        }
        __syncwarp();                      // chunk c visible to all lanes

        const int ti = c >> 4, sub = c & 15;
        const float4* buf = (const float4*)&stage_s[wid * 512 + (c & 1) * 256];
        float4 v0 = buf[g3 * 16 + s8];
        float4 v1 = buf[g3 * 16 + s8 + 8];
        float s = v0.x * u4a.x + v0.y * u4a.y + v0.z * u4a.z + v0.w * u4a.w
                + v1.x * u4b.x + v1.y * u4b.y + v1.z * u4b.z + v1.w * u4b.w;
        #pragma unroll
        for (int off = 4; off > 0; off >>= 1)
            s += __shfl_xor_sync(0xffffffffu, s, off);
        if (s8 == 0) {
            int j = wid * 64 + sub * 4 + g3;
            float val = ei_s[ti] + ej_s[j] + s;
            val = fmaxf(val, ALPHA * val);     // leaky relu (alpha > 0)
            float ev = __expf(val);
            es_f[j * TI + ti] = ev;
            psum += ev;
        }
        if ((c & 15) == 15) {                  // end of this ti's stripe
            psum += __shfl_xor_sync(0xffffffffu, psum, 8);
            psum += __shfl_xor_sync(0xffffffffu, psum, 16);
            if (lane == 0) wsum[ti * 8 + wid] = psum;
            psum = 0.f;
        }
    }
    __syncthreads();

    if (t < TI) {
        float ss = wsum[t * 8 + 0];
        #pragma unroll
        for (int w = 1; w < 8; w++) ss += wsum[t * 8 + w];
        rowsum[t] = ss;
    }
    __syncthreads();   // pool reuse barrier (ej_s -> red_c) + rowsum ready

    // --- Phase C: acc[ti] = sum_j p[ti][j] * Wh[b,j,o], j split in 4 groups ---
    float* red_c = pool;
    {
        const int g = t >> 6, o = t & 63;
        const float* WhB = g_Wh + (size_t)b * N_ * FOUT;
        float acc[TI];
        #pragma unroll
        for (int ti = 0; ti < TI; ti++) acc[ti] = 0.f;
        const int jbase = g * 128;
        #pragma unroll 2
        for (int jj = 0; jj < 128; jj++) {
            int j = jbase + jj;
            float w = __ldg(WhB + (size_t)j * FOUT + o);
            float4 ea = *(const float4*)&es_f[j * TI];
            float4 eb = *(const float4*)&es_f[j * TI + 4];
            acc[0] += ea.x * w; acc[1] += ea.y * w;
            acc[2] += ea.z * w; acc[3] += ea.w * w;
            acc[4] += eb.x * w; acc[5] += eb.y * w;
            acc[6] += eb.z * w; acc[7] += eb.w * w;
        }
        #pragma unroll
        for (int ti = 0; ti < TI; ti++)
            red_c[(g * TI + ti) * FOUT + o] = acc[ti];
    }
    __syncthreads();
    #pragma unroll
    for (int rep = 0; rep < 2; rep++) {
        int idx = t + rep * 256;
        int ti = idx >> 6, o = idx & 63;
        float r = red_c[(0 * TI + ti) * FOUT + o]
                + red_c[(1 * TI + ti) * FOUT + o]
                + red_c[(2 * TI + ti) * FOUT + o]
                + red_c[(3 * TI + ti) * FOUT + o];
        r *= __frcp_rn(rowsum[ti]);
        out[((size_t)(b * N_ + i0 + ti)) * FOUT + o] = r;
    }
}

// ---------------------------------------------------------------------------
extern "C" void kernel_launch(void* const* d_in, const int* in_sizes, int n_in,
                              void* d_out, int out_size)
{
    const float* h    = (const float*)d_in[0];   // [8,512,128]
    const float* edge = (const float*)d_in[1];   // [8,512,512,64]
    const float* W    = (const float*)d_in[2];   // [1,128,64]
    const float* U    = (const float*)d_in[3];   // [1,64]
    const float* a    = (const float*)d_in[4];   // [1,129]
    float* out = (float*)d_out;                  // [8,512,64]

    gat_stage1<<<B_ * (N_ / 8), 256>>>(h, W, a);
    gat_stage2<<<B_ * (N_ / TI), 256>>>(edge, U, a, out);
}

// round 8
// speedup vs baseline: 1.5268x; 1.1886x over previous
#include <cuda_runtime.h>
#include <cstdint>
#include <cstddef>

#define B_   8
#define N_   512
#define FIN  128
#define FOUT 64
#define ALPHA 0.2f

// Scratch (no allocations allowed)
__device__ float g_Wh[B_ * N_ * FOUT];   // 1 MB
__device__ float g_ei[B_ * N_];
__device__ float g_ej[B_ * N_];

// ---------------------------------------------------------------------------
// Stage 1: Wh = h @ W ; e_i = Wh·a_i ; e_j = Wh·a_j
// ---------------------------------------------------------------------------
__global__ __launch_bounds__(256)
void gat_stage1(const float* __restrict__ h,
                const float* __restrict__ W,
                const float* __restrict__ a)
{
    __shared__ float Wt[FOUT * 129];
    __shared__ float h_s[8 * FIN];
    __shared__ float wh_s[8 * 65];

    const int t = threadIdx.x;
    const int b  = blockIdx.x >> 6;
    const int i0 = (blockIdx.x & 63) * 8;

    for (int idx = t; idx < FIN * FOUT; idx += 256) {
        int k = idx >> 6, o = idx & 63;
        Wt[o * 129 + k] = W[idx];
    }
    {
        const float4* hb = (const float4*)(h + ((size_t)(b * N_ + i0)) * FIN);
        float4* hs4 = (float4*)h_s;
        for (int idx = t; idx < 8 * FIN / 4; idx += 256) hs4[idx] = hb[idx];
    }
    __syncthreads();

    const int o = t & 63, grp = t >> 6;
    float acc0 = 0.f, acc1 = 0.f;
    const float* hb = h_s + grp * 2 * FIN;
    #pragma unroll 8
    for (int k = 0; k < FIN; k++) {
        float w = Wt[o * 129 + k];
        acc0 += hb[k] * w;
        acc1 += hb[FIN + k] * w;
    }
    wh_s[(grp * 2 + 0) * 65 + o] = acc0;
    wh_s[(grp * 2 + 1) * 65 + o] = acc1;
    g_Wh[((size_t)(b * N_ + i0 + grp * 2 + 0)) * FOUT + o] = acc0;
    g_Wh[((size_t)(b * N_ + i0 + grp * 2 + 1)) * FOUT + o] = acc1;
    __syncthreads();

    const int wid = t >> 5, lane = t & 31;
    {
        int row = wid;
        float v1 = wh_s[row * 65 + lane];
        float v2 = wh_s[row * 65 + lane + 32];
        float si = v1 * a[lane]      + v2 * a[lane + 32];
        float sj = v1 * a[64 + lane] + v2 * a[96 + lane];
        #pragma unroll
        for (int off = 16; off > 0; off >>= 1) {
            si += __shfl_xor_sync(0xffffffffu, si, off);
            sj += __shfl_xor_sync(0xffffffffu, sj, off);
        }
        if (lane == 0) {
            g_ei[b * N_ + i0 + row] = si;
            g_ej[b * N_ + i0 + row] = sj;
        }
    }
}

// ---------------------------------------------------------------------------
// Stage 2: FULLY fused: edge stream -> logits -> exp -> numerator rank-1
// accumulation, barrier-free hot loop. Softmax normalization in epilogue.
// Grid: 512 CTAs, 256 threads, TI = 8. Warp w owns j in [w*64,(w+1)*64).
// Chunk = 4 j-rows x 1 ti (1 KB). sub outer / ti inner: Wh rows for the
// chunk's 4 j live in registers and are reused across all 8 ti.
// ---------------------------------------------------------------------------
#define TI 8

__device__ __forceinline__ void cp_async16(uint32_t dst, const float* src) {
    asm volatile("cp.async.cg.shared.global [%0], [%1], 16;" :: "r"(dst), "l"(src));
}

__global__ __launch_bounds__(256, 4)
void gat_stage2(const float* __restrict__ edge,
                const float* __restrict__ U,
                const float* __restrict__ a,
                float* __restrict__ out)
{
    __shared__ __align__(16) float stage_s[8 * 2 * 256];   // [warp][buf][1KB] 16 KB
    __shared__ __align__(16) float red_w[8 * TI * FOUT];   // [warp][ti][o]   16 KB
    __shared__ float  ej_s[N_];                            // 2 KB
    __shared__ float4 u_s[16];
    __shared__ float  ei_s[TI];
    __shared__ float  wsum[TI * 8];
    __shared__ float  rowsum[TI];

    const int t    = threadIdx.x;
    const int b    = blockIdx.x >> 6;
    const int i0   = (blockIdx.x & 63) * TI;
    const int wid  = t >> 5, lane = t & 31;
    const int g3   = lane >> 3, s8 = lane & 7;

    const float a_e = __ldg(a + 2 * FOUT);
    if (t < 16) {
        float4 u = ((const float4*)U)[t];
        u.x *= a_e; u.y *= a_e; u.z *= a_e; u.w *= a_e;
        u_s[t] = u;
    }
    if (t < TI) ei_s[t] = g_ei[b * N_ + i0 + t];
    ej_s[t]       = g_ej[b * N_ + t];
    ej_s[t + 256] = g_ej[b * N_ + t + 256];
    __syncthreads();

    const float4 u4a = u_s[s8];
    const float4 u4b = u_s[s8 + 8];
    const float* WhB = g_Wh + (size_t)b * N_ * FOUT;
    const int jb = wid * 64;

    const float* wbase = edge + ((size_t)(b * N_ + i0) * N_ + jb) * FOUT;
    const uint32_t stg =
        (uint32_t)__cvta_generic_to_shared(&stage_s[wid * 512]) + lane * 16;

    // prologue: stream chunk 0 (sub=0, ti=0)
    cp_async16(stg,       wbase + lane * 4);
    cp_async16(stg + 512, wbase + lane * 4 + 128);
    asm volatile("cp.async.commit_group;" ::: "memory");

    float acc0[TI], acc1[TI], psum[TI];
    #pragma unroll
    for (int ti = 0; ti < TI; ti++) { acc0[ti] = 0.f; acc1[ti] = 0.f; psum[ti] = 0.f; }

    float eival[TI];
    #pragma unroll
    for (int ti = 0; ti < TI; ti++) eival[ti] = ei_s[ti];

    for (int sub = 0; sub < 16; sub++) {
        // Wh rows for this chunk's 4 j, register-cached, reused for 8 ti.
        // Issued before the first stream wait -> L2 latency overlapped.
        float whA[4], whB4[4];
        #pragma unroll
        for (int k = 0; k < 4; k++) {
            const float* wr = WhB + (size_t)(jb + sub * 4 + k) * FOUT;
            whA[k]  = __ldg(wr + lane);
            whB4[k] = __ldg(wr + lane + 32);
        }
        const float ejv = ej_s[jb + sub * 4 + g3];

        #pragma unroll
        for (int ti = 0; ti < TI; ti++) {
            const int c = sub * 8 + ti;
            if (c < 127) {
                const int cn = c + 1;
                const int subn = cn >> 3, tin = cn & 7;
                const float* gsrc = wbase + tin * (N_ * FOUT)
                                          + subn * (4 * FOUT) + lane * 4;
                uint32_t dst = stg + (cn & 1) * 1024;
                cp_async16(dst,       gsrc);
                cp_async16(dst + 512, gsrc + 128);
                asm volatile("cp.async.commit_group;" ::: "memory");
                asm volatile("cp.async.wait_group 1;" ::: "memory");
            } else {
                asm volatile("cp.async.wait_group 0;" ::: "memory");
            }
            __syncwarp();

            const float4* buf = (const float4*)&stage_s[wid * 512 + (c & 1) * 256];
            float4 v0 = buf[g3 * 16 + s8];
            float4 v1 = buf[g3 * 16 + s8 + 8];
            float s = v0.x * u4a.x + v0.y * u4a.y + v0.z * u4a.z + v0.w * u4a.w
                    + v1.x * u4b.x + v1.y * u4b.y + v1.z * u4b.z + v1.w * u4b.w;
            #pragma unroll
            for (int off = 4; off > 0; off >>= 1)
                s += __shfl_xor_sync(0xffffffffu, s, off);
            // all lanes of the 8-lane group now hold the full dot for row g3
            float val = eival[ti] + ejv + s;
            val = fmaxf(val, ALPHA * val);      // leaky relu (alpha > 0)
            float ev = __expf(val);
            if (s8 == 0) psum[ti] += ev;
            // rank-1 update: broadcast 4 evs, FMA into per-warp numerator
            #pragma unroll
            for (int k = 0; k < 4; k++) {
                float evk = __shfl_sync(0xffffffffu, ev, k * 8);
                acc0[ti] = fmaf(evk, whA[k],  acc0[ti]);
                acc1[ti] = fmaf(evk, whB4[k], acc1[ti]);
            }
            __syncwarp();    // protect stage buffer reuse
        }
    }

    // write per-warp numerators + rowsum partials
    #pragma unroll
    for (int ti = 0; ti < TI; ti++) {
        red_w[(wid * TI + ti) * FOUT + lane]      = acc0[ti];
        red_w[(wid * TI + ti) * FOUT + lane + 32] = acc1[ti];
        float p = psum[ti];
        p += __shfl_xor_sync(0xffffffffu, p, 8);
        p += __shfl_xor_sync(0xffffffffu, p, 16);
        if (lane == 0) wsum[ti * 8 + wid] = p;
    }
    __syncthreads();

    if (t < TI) {
        float ss = wsum[t * 8 + 0];
        #pragma unroll
        for (int w = 1; w < 8; w++) ss += wsum[t * 8 + w];
        rowsum[t] = ss;
    }
    __syncthreads();

    // epilogue: 512 outputs, 2 per thread: sum 8 warps, normalize
    #pragma unroll
    for (int rep = 0; rep < 2; rep++) {
        int idx = t + rep * 256;
        int ti = idx >> 6, o = idx & 63;
        float r = 0.f;
        #pragma unroll
        for (int w = 0; w < 8; w++)
            r += red_w[(w * TI + ti) * FOUT + o];
        r *= __frcp_rn(rowsum[ti]);
        out[((size_t)(b * N_ + i0 + ti)) * FOUT + o] = r;
    }
}

// ---------------------------------------------------------------------------
extern "C" void kernel_launch(void* const* d_in, const int* in_sizes, int n_in,
                              void* d_out, int out_size)
{
    const float* h    = (const float*)d_in[0];   // [8,512,128]
    const float* edge = (const float*)d_in[1];   // [8,512,512,64]
    const float* W    = (const float*)d_in[2];   // [1,128,64]
    const float* U    = (const float*)d_in[3];   // [1,64]
    const float* a    = (const float*)d_in[4];   // [1,129]
    float* out = (float*)d_out;                  // [8,512,64]

    gat_stage1<<<B_ * (N_ / 8), 256>>>(h, W, a);
    gat_stage2<<<B_ * (N_ / TI), 256>>>(edge, U, a, out);
}